// round 7
// baseline (speedup 1.0000x reference)
#include <cuda_runtime.h>
#include <cuda_fp16.h>
#include <math.h>
#include <stdint.h>

// ---------------------------------------------------------------------------
// ResidualDenoiser via HMMA (mma.sync fp16, fp32 acc), pure fp16 inference.
// CTA tile 128x256 (warp tile 64x64) for layers 0-2; 128x128 for layer 3.
//
// Activation buffer (width 3328, fp16): [ h2 (1024) | h1 (1024) | h0 (1024) | x (256) ]
// ---------------------------------------------------------------------------

#define B_ROWS 8192
#define ACT_W  3328
#define NSEG   10
#define EPS    1e-5f

#define TBM 128
#define KC  32
#define NSTAGE 4
#define ROWB 80                  // padded row stride (bytes) for 64B of k data
#define ATILEB (128 * ROWB)      // A tile bytes

// weight concat offsets (elements)
#define WOFF0 0
#define WOFF1 262144
#define WOFF2 1572864
#define WOFF3 3932160
#define WTOT  4784128

__device__ __half g_act[(size_t)B_ROWS * ACT_W];
__device__ __half g_w[WTOT];
__device__ float  g_logits[(size_t)B_ROWS * 256];

__device__ __forceinline__ uint32_t smem_u32(const void* p) {
    uint32_t a;
    asm("{ .reg .u64 t; cvta.to.shared.u64 t, %1; cvt.u32.u64 %0, t; }" : "=r"(a) : "l"(p));
    return a;
}

#define CP_ASYNC16(dst, src) \
    asm volatile("cp.async.cg.shared.global [%0], [%1], 16;" :: "r"(dst), "l"(src))
#define CP_COMMIT()  asm volatile("cp.async.commit_group;" ::: "memory")
#define CP_WAIT3()   asm volatile("cp.async.wait_group 3;" ::: "memory")
#define CP_WAIT0()   asm volatile("cp.async.wait_group 0;" ::: "memory")

#define LDSM_X4(r0, r1, r2, r3, a) \
    asm volatile("ldmatrix.sync.aligned.m8n8.x4.shared.b16 {%0,%1,%2,%3}, [%4];" \
        : "=r"(r0), "=r"(r1), "=r"(r2), "=r"(r3) : "r"(a))

#define MMA_F16(d, a, b) \
    asm volatile("mma.sync.aligned.m16n8k16.row.col.f32.f16.f16.f32 " \
        "{%0,%1,%2,%3}, {%4,%5,%6,%7}, {%8,%9}, {%0,%1,%2,%3};" \
        : "+f"((d)[0]), "+f"((d)[1]), "+f"((d)[2]), "+f"((d)[3]) \
        : "r"((a)[0]), "r"((a)[1]), "r"((a)[2]), "r"((a)[3]), \
          "r"((b)[0]), "r"((b)[1]))

// ---------------------------------------------------------------------------
// GEMM: C[r,f] = sum_k A[r,k]*W[f,k]
//   NT = n-tiles (8-wide) per warp: NT=8 -> TBN=256, NT=4 -> TBN=128.
//   2 warps over M (64 rows), 4 warps over N, 256 threads.
//   BN=true : bias+BN+ReLU -> fp16 out (row stride ACT_W)
//   BN=false: bias         -> fp32 out (row stride 256)
// ---------------------------------------------------------------------------
template <int NT, bool BN>
__global__ __launch_bounds__(256)
void mma_gemm(const __half* __restrict__ A,
              const __half* __restrict__ Wh,
              const float* __restrict__ bias,
              const float* __restrict__ gg, const float* __restrict__ be,
              const float* __restrict__ rm, const float* __restrict__ rv,
              __half* __restrict__ Ch,
              float* __restrict__ Cf, int K)
{
    constexpr int TBN    = 4 * NT * 8;               // 256 or 128
    constexpr int STAGEB = (128 + TBN) * ROWB;       // A tile + W tile
    constexpr int CH     = (128 + TBN) * 4 / 256;    // cp.async chunks per thread

    extern __shared__ char smem[];
    const uint32_t sbuf = smem_u32(smem);

    const int tid    = threadIdx.x;
    const int lane   = tid & 31;
    const int wid    = tid >> 5;
    const int warp_m = wid & 1;        // 2 warps over M (64 rows each)
    const int warp_n = wid >> 1;       // 4 warps over N (NT*8 cols each)
    const int row0   = blockIdx.y * TBM;
    const int col0   = blockIdx.x * TBN;

    const int n_iter = K / KC;

    float acc[4][NT][4];
    #pragma unroll
    for (int i = 0; i < 4; i++)
        #pragma unroll
        for (int j = 0; j < NT; j++)
            #pragma unroll
            for (int l = 0; l < 4; l++)
                acc[i][j][l] = 0.f;

    // stage loader: (128 + TBN) rows * 4 chunks of 16B
    auto load_stage = [&](int s) {
        const int k0  = s * KC;
        const uint32_t sb = sbuf + (s % NSTAGE) * STAGEB;
        #pragma unroll
        for (int i = 0; i < CH; i++) {
            const int idx = tid + (i << 8);
            const int c   = idx & 3;               // 16B chunk
            if (idx < 512) {
                const int r = idx >> 2;
                CP_ASYNC16(sb + r * ROWB + c * 16,
                           A + (size_t)(row0 + r) * ACT_W + k0 + c * 8);
            } else {
                const int r = (idx - 512) >> 2;
                CP_ASYNC16(sb + ATILEB + r * ROWB + c * 16,
                           Wh + (size_t)(col0 + r) * K + k0 + c * 8);
            }
        }
    };

    // ldmatrix per-lane base offsets
    const uint32_t a_off = (uint32_t)((warp_m * 64 + (lane & 15)) * ROWB + (lane >> 4) * 16);
    const uint32_t b_off = (uint32_t)((warp_n * (NT * 8) + (lane >> 4) * 8 + (lane & 7)) * ROWB
                                      + ((lane >> 3) & 1) * 16);

    // prologue: stages 0,1,2
    load_stage(0); CP_COMMIT();
    load_stage(1); CP_COMMIT();
    load_stage(2); CP_COMMIT();

    for (int it = 0; it < n_iter; it++) {
        if (it + 3 < n_iter) load_stage(it + 3);
        CP_COMMIT();
        CP_WAIT3();
        __syncthreads();

        const uint32_t sb = sbuf + (it % NSTAGE) * STAGEB;
        #pragma unroll
        for (int kk = 0; kk < 2; kk++) {         // two k16 steps
            uint32_t ah[4][4], bh[NT][2];
            #pragma unroll
            for (int mt = 0; mt < 4; mt++) {
                const uint32_t aa = sb + a_off + mt * (16 * ROWB) + kk * 32;
                LDSM_X4(ah[mt][0], ah[mt][1], ah[mt][2], ah[mt][3], aa);
            }
            #pragma unroll
            for (int bt = 0; bt < NT / 2; bt++) {
                const uint32_t ba = sb + ATILEB + b_off + bt * (16 * ROWB) + kk * 32;
                uint32_t r0, r1, r2, r3;
                LDSM_X4(r0, r1, r2, r3, ba);
                bh[bt * 2][0] = r0;     bh[bt * 2][1] = r1;
                bh[bt * 2 + 1][0] = r2; bh[bt * 2 + 1][1] = r3;
            }
            #pragma unroll
            for (int mt = 0; mt < 4; mt++)
                #pragma unroll
                for (int nt = 0; nt < NT; nt++)
                    MMA_F16(acc[mt][nt], ah[mt], bh[nt]);
        }
        __syncthreads();
    }
    CP_WAIT0();

    // ------------------------------ epilogue ------------------------------
    #pragma unroll
    for (int nt = 0; nt < NT; nt++) {
        const int f = col0 + warp_n * (NT * 8) + nt * 8 + (lane & 3) * 2;
        const float bs0 = bias[f], bs1 = bias[f + 1];
        float sc0 = 0.f, sh0 = 0.f, sc1 = 0.f, sh1 = 0.f;
        if (BN) {
            sc0 = gg[f]     * rsqrtf(rv[f]     + EPS);
            sc1 = gg[f + 1] * rsqrtf(rv[f + 1] + EPS);
            sh0 = be[f]     - rm[f]     * sc0;
            sh1 = be[f + 1] - rm[f + 1] * sc1;
        }
        #pragma unroll
        for (int mt = 0; mt < 4; mt++) {
            const int r = row0 + warp_m * 64 + mt * 16 + (lane >> 2);
            #pragma unroll
            for (int half = 0; half < 2; half++) {
                const int rr = r + half * 8;
                float v0 = acc[mt][nt][half * 2]     + bs0;
                float v1 = acc[mt][nt][half * 2 + 1] + bs1;
                if (BN) {
                    v0 = fmaxf(fmaf(v0, sc0, sh0), 0.f);
                    v1 = fmaxf(fmaf(v1, sc1, sh1), 0.f);
                    __half2 hp; hp.x = __float2half(v0); hp.y = __float2half(v1);
                    *reinterpret_cast<__half2*>(Ch + (size_t)rr * ACT_W + f) = hp;
                } else {
                    float2 o; o.x = v0; o.y = v1;
                    *reinterpret_cast<float2*>(Cf + (size_t)rr * 256 + f) = o;
                }
            }
        }
    }
}

// ---------------------------------------------------------------------------
// conversions (vectorized: 8 elems / thread)
// ---------------------------------------------------------------------------
__global__ void cvt_w_one(const float* __restrict__ src,
                          __half* __restrict__ dst, int n)
{
    int i = (blockIdx.x * blockDim.x + threadIdx.x) * 8;
    if (i < n) {
        float4 a = *reinterpret_cast<const float4*>(src + i);
        float4 b = *reinterpret_cast<const float4*>(src + i + 4);
        __half2 h[4];
        h[0] = __floats2half2_rn(a.x, a.y);
        h[1] = __floats2half2_rn(a.z, a.w);
        h[2] = __floats2half2_rn(b.x, b.y);
        h[3] = __floats2half2_rn(b.z, b.w);
        *reinterpret_cast<uint4*>(dst + i) = *reinterpret_cast<uint4*>(h);
    }
}

__global__ void cvt_x_kernel(const float* __restrict__ x)
{
    int i = (blockIdx.x * blockDim.x + threadIdx.x) * 8;      // over 8192*256
    int r = i >> 8;
    int c = i & 255;
    float4 a = *reinterpret_cast<const float4*>(x + i);
    float4 b = *reinterpret_cast<const float4*>(x + i + 4);
    __half2 h[4];
    h[0] = __floats2half2_rn(a.x, a.y);
    h[1] = __floats2half2_rn(a.z, a.w);
    h[2] = __floats2half2_rn(b.x, b.y);
    h[3] = __floats2half2_rn(b.z, b.w);
    *reinterpret_cast<uint4*>(g_act + (size_t)r * ACT_W + 3072 + c) =
        *reinterpret_cast<uint4*>(h);
}

// ---------------------------------------------------------------------------
// Segmented softmax (one block per row)
// ---------------------------------------------------------------------------
__global__ void seg_softmax_kernel(const int* __restrict__ seg_ids,
                                   float* __restrict__ out)
{
    __shared__ float vals[256];
    __shared__ int   sseg[256];
    __shared__ float smax[NSEG];
    __shared__ float ssum[NSEG];

    const int row = blockIdx.x;
    const int t   = threadIdx.x;

    float v = g_logits[(size_t)row * 256 + t];
    vals[t] = v;
    sseg[t] = seg_ids[t];
    __syncthreads();

    if (t < NSEG) {
        float m = -3.402823466e+38f;
        for (int i = 0; i < 256; i++)
            if (sseg[i] == t) m = fmaxf(m, vals[i]);
        smax[t] = m;
    }
    __syncthreads();

    const int s = sseg[t];
    float e = expf(v - smax[s]);
    vals[t] = e;
    __syncthreads();

    if (t < NSEG) {
        float sum = 0.f;
        for (int i = 0; i < 256; i++)
            if (sseg[i] == t) sum += vals[i];
        ssum[t] = sum;
    }
    __syncthreads();

    out[(size_t)row * 256 + t] = e / ssum[s];
}

// ---------------------------------------------------------------------------
// Launch
// ---------------------------------------------------------------------------
#define SMEM_NT8 (NSTAGE * (128 + 256) * ROWB)   // 122880
#define SMEM_NT4 (NSTAGE * (128 + 128) * ROWB)   // 81920

extern "C" void kernel_launch(void* const* d_in, const int* in_sizes, int n_in,
                              void* d_out, int out_size)
{
    const float* x   = (const float*)d_in[0];
    const float* W0  = (const float*)d_in[1];
    const float* b0  = (const float*)d_in[2];
    const float* g0  = (const float*)d_in[3];
    const float* be0 = (const float*)d_in[4];
    const float* rm0 = (const float*)d_in[5];
    const float* rv0 = (const float*)d_in[6];
    const float* W1  = (const float*)d_in[7];
    const float* b1  = (const float*)d_in[8];
    const float* g1  = (const float*)d_in[9];
    const float* be1 = (const float*)d_in[10];
    const float* rm1 = (const float*)d_in[11];
    const float* rv1 = (const float*)d_in[12];
    const float* W2  = (const float*)d_in[13];
    const float* b2  = (const float*)d_in[14];
    const float* g2  = (const float*)d_in[15];
    const float* be2 = (const float*)d_in[16];
    const float* rm2 = (const float*)d_in[17];
    const float* rv2 = (const float*)d_in[18];
    const float* W3  = (const float*)d_in[19];
    const float* b3  = (const float*)d_in[20];
    const int*   seg = (const int*)d_in[21];

    __half *act = nullptr, *wh = nullptr;
    float* logits = nullptr;
    cudaGetSymbolAddress((void**)&act, g_act);
    cudaGetSymbolAddress((void**)&wh, g_w);
    cudaGetSymbolAddress((void**)&logits, g_logits);

    cudaFuncSetAttribute(mma_gemm<8, true>,  cudaFuncAttributeMaxDynamicSharedMemorySize, SMEM_NT8);
    cudaFuncSetAttribute(mma_gemm<4, false>, cudaFuncAttributeMaxDynamicSharedMemorySize, SMEM_NT4);

    // prologue: conversions (all sizes divisible by 8*256)
    cvt_x_kernel<<<(B_ROWS * 256) / (256 * 8), 256>>>(x);
    cvt_w_one<<<(1024 * 256) / (256 * 8), 256>>>(W0, wh + WOFF0, 1024 * 256);
    cvt_w_one<<<(1024 * 1280) / (256 * 8), 256>>>(W1, wh + WOFF1, 1024 * 1280);
    cvt_w_one<<<(1024 * 2304) / (256 * 8), 256>>>(W2, wh + WOFF2, 1024 * 2304);
    cvt_w_one<<<(256 * 3328) / (256 * 8), 256>>>(W3, wh + WOFF3, 256 * 3328);

    dim3 blk(256);
    dim3 grid256n(1024 / 256, B_ROWS / TBM);   // (4, 64) for NT=8 layers
    dim3 grid128n(256 / 128, B_ROWS / TBM);    // (2, 64) for layer 3

    mma_gemm<8, true><<<grid256n, blk, SMEM_NT8>>>(act + 3072, wh + WOFF0,
                                                   b0, g0, be0, rm0, rv0,
                                                   act + 2048, nullptr, 256);
    mma_gemm<8, true><<<grid256n, blk, SMEM_NT8>>>(act + 2048, wh + WOFF1,
                                                   b1, g1, be1, rm1, rv1,
                                                   act + 1024, nullptr, 1280);
    mma_gemm<8, true><<<grid256n, blk, SMEM_NT8>>>(act + 1024, wh + WOFF2,
                                                   b2, g2, be2, rm2, rv2,
                                                   act, nullptr, 2304);
    mma_gemm<4, false><<<grid128n, blk, SMEM_NT4>>>(act, wh + WOFF3,
                                                    b3, nullptr, nullptr, nullptr, nullptr,
                                                    nullptr, logits, 3328);

    seg_softmax_kernel<<<B_ROWS, 256>>>(seg, (float*)d_out);
}

// round 8
// speedup vs baseline: 1.0007x; 1.0007x over previous
#include <cuda_runtime.h>
#include <cuda_fp16.h>
#include <math.h>
#include <stdint.h>

// ---------------------------------------------------------------------------
// ResidualDenoiser via HMMA (mma.sync fp16, fp32 acc), pure fp16 inference.
// CTA tile 128x256 (warp tile 64x64) for layers 0-2; 128x128 for layer 3.
//
// Activation buffer (width 3328, fp16): [ h2 (1024) | h1 (1024) | h0 (1024) | x (256) ]
// ---------------------------------------------------------------------------

#define B_ROWS 8192
#define ACT_W  3328
#define NSEG   10
#define EPS    1e-5f

#define TBM 128
#define KC  32
#define NSTAGE 4
#define ROWB 80                  // padded row stride (bytes) for 64B of k data
#define ATILEB (128 * ROWB)      // A tile bytes

// weight concat offsets (elements)
#define WOFF0 0
#define WOFF1 262144
#define WOFF2 1572864
#define WOFF3 3932160
#define WTOT  4784128

__device__ __half g_act[(size_t)B_ROWS * ACT_W];
__device__ __half g_w[WTOT];
__device__ float  g_logits[(size_t)B_ROWS * 256];

__device__ __forceinline__ uint32_t smem_u32(const void* p) {
    uint32_t a;
    asm("{ .reg .u64 t; cvta.to.shared.u64 t, %1; cvt.u32.u64 %0, t; }" : "=r"(a) : "l"(p));
    return a;
}

#define CP_ASYNC16(dst, src) \
    asm volatile("cp.async.cg.shared.global [%0], [%1], 16;" :: "r"(dst), "l"(src))
#define CP_COMMIT()  asm volatile("cp.async.commit_group;" ::: "memory")
#define CP_WAIT3()   asm volatile("cp.async.wait_group 3;" ::: "memory")
#define CP_WAIT0()   asm volatile("cp.async.wait_group 0;" ::: "memory")

#define LDSM_X4(r0, r1, r2, r3, a) \
    asm volatile("ldmatrix.sync.aligned.m8n8.x4.shared.b16 {%0,%1,%2,%3}, [%4];" \
        : "=r"(r0), "=r"(r1), "=r"(r2), "=r"(r3) : "r"(a))

#define MMA_F16(d, a, b) \
    asm volatile("mma.sync.aligned.m16n8k16.row.col.f32.f16.f16.f32 " \
        "{%0,%1,%2,%3}, {%4,%5,%6,%7}, {%8,%9}, {%0,%1,%2,%3};" \
        : "+f"((d)[0]), "+f"((d)[1]), "+f"((d)[2]), "+f"((d)[3]) \
        : "r"((a)[0]), "r"((a)[1]), "r"((a)[2]), "r"((a)[3]), \
          "r"((b)[0]), "r"((b)[1]))

// ---------------------------------------------------------------------------
// GEMM: C[r,f] = sum_k A[r,k]*W[f,k]
//   NT = n-tiles (8-wide) per warp: NT=8 -> TBN=256, NT=4 -> TBN=128.
//   2 warps over M (64 rows), 4 warps over N, 256 threads.
//   BN=true : bias+BN+ReLU -> fp16 out (row stride ACT_W)
//   BN=false: bias         -> fp32 out (row stride 256)
// ---------------------------------------------------------------------------
template <int NT, bool BN>
__global__ __launch_bounds__(256)
void mma_gemm(const __half* __restrict__ A,
              const __half* __restrict__ Wh,
              const float* __restrict__ bias,
              const float* __restrict__ gg, const float* __restrict__ be,
              const float* __restrict__ rm, const float* __restrict__ rv,
              __half* __restrict__ Ch,
              float* __restrict__ Cf, int K)
{
    constexpr int TBN    = 4 * NT * 8;               // 256 or 128
    constexpr int STAGEB = (128 + TBN) * ROWB;       // A tile + W tile
    constexpr int CH     = (128 + TBN) * 4 / 256;    // cp.async chunks per thread

    extern __shared__ char smem[];
    const uint32_t sbuf = smem_u32(smem);

    const int tid    = threadIdx.x;
    const int lane   = tid & 31;
    const int wid    = tid >> 5;
    const int warp_m = wid & 1;        // 2 warps over M (64 rows each)
    const int warp_n = wid >> 1;       // 4 warps over N (NT*8 cols each)
    const int row0   = blockIdx.y * TBM;
    const int col0   = blockIdx.x * TBN;

    const int n_iter = K / KC;

    float acc[4][NT][4];
    #pragma unroll
    for (int i = 0; i < 4; i++)
        #pragma unroll
        for (int j = 0; j < NT; j++)
            #pragma unroll
            for (int l = 0; l < 4; l++)
                acc[i][j][l] = 0.f;

    // stage loader: (128 + TBN) rows * 4 chunks of 16B
    auto load_stage = [&](int s) {
        const int k0  = s * KC;
        const uint32_t sb = sbuf + (s % NSTAGE) * STAGEB;
        #pragma unroll
        for (int i = 0; i < CH; i++) {
            const int idx = tid + (i << 8);
            const int c   = idx & 3;               // 16B chunk
            if (idx < 512) {
                const int r = idx >> 2;
                CP_ASYNC16(sb + r * ROWB + c * 16,
                           A + (size_t)(row0 + r) * ACT_W + k0 + c * 8);
            } else {
                const int r = (idx - 512) >> 2;
                CP_ASYNC16(sb + ATILEB + r * ROWB + c * 16,
                           Wh + (size_t)(col0 + r) * K + k0 + c * 8);
            }
        }
    };

    // ldmatrix per-lane base offsets
    const uint32_t a_off = (uint32_t)((warp_m * 64 + (lane & 15)) * ROWB + (lane >> 4) * 16);
    const uint32_t b_off = (uint32_t)((warp_n * (NT * 8) + (lane >> 4) * 8 + (lane & 7)) * ROWB
                                      + ((lane >> 3) & 1) * 16);

    // prologue: stages 0,1,2
    load_stage(0); CP_COMMIT();
    load_stage(1); CP_COMMIT();
    load_stage(2); CP_COMMIT();

    for (int it = 0; it < n_iter; it++) {
        if (it + 3 < n_iter) load_stage(it + 3);
        CP_COMMIT();
        CP_WAIT3();
        __syncthreads();

        const uint32_t sb = sbuf + (it % NSTAGE) * STAGEB;
        #pragma unroll
        for (int kk = 0; kk < 2; kk++) {         // two k16 steps
            uint32_t ah[4][4], bh[NT][2];
            #pragma unroll
            for (int mt = 0; mt < 4; mt++) {
                const uint32_t aa = sb + a_off + mt * (16 * ROWB) + kk * 32;
                LDSM_X4(ah[mt][0], ah[mt][1], ah[mt][2], ah[mt][3], aa);
            }
            #pragma unroll
            for (int bt = 0; bt < NT / 2; bt++) {
                const uint32_t ba = sb + ATILEB + b_off + bt * (16 * ROWB) + kk * 32;
                uint32_t r0, r1, r2, r3;
                LDSM_X4(r0, r1, r2, r3, ba);
                bh[bt * 2][0] = r0;     bh[bt * 2][1] = r1;
                bh[bt * 2 + 1][0] = r2; bh[bt * 2 + 1][1] = r3;
            }
            #pragma unroll
            for (int mt = 0; mt < 4; mt++)
                #pragma unroll
                for (int nt = 0; nt < NT; nt++)
                    MMA_F16(acc[mt][nt], ah[mt], bh[nt]);
        }
        __syncthreads();
    }
    CP_WAIT0();

    // ------------------------------ epilogue ------------------------------
    #pragma unroll
    for (int nt = 0; nt < NT; nt++) {
        const int f = col0 + warp_n * (NT * 8) + nt * 8 + (lane & 3) * 2;
        const float bs0 = bias[f], bs1 = bias[f + 1];
        float sc0 = 0.f, sh0 = 0.f, sc1 = 0.f, sh1 = 0.f;
        if (BN) {
            sc0 = gg[f]     * rsqrtf(rv[f]     + EPS);
            sc1 = gg[f + 1] * rsqrtf(rv[f + 1] + EPS);
            sh0 = be[f]     - rm[f]     * sc0;
            sh1 = be[f + 1] - rm[f + 1] * sc1;
        }
        #pragma unroll
        for (int mt = 0; mt < 4; mt++) {
            const int r = row0 + warp_m * 64 + mt * 16 + (lane >> 2);
            #pragma unroll
            for (int half = 0; half < 2; half++) {
                const int rr = r + half * 8;
                float v0 = acc[mt][nt][half * 2]     + bs0;
                float v1 = acc[mt][nt][half * 2 + 1] + bs1;
                if (BN) {
                    v0 = fmaxf(fmaf(v0, sc0, sh0), 0.f);
                    v1 = fmaxf(fmaf(v1, sc1, sh1), 0.f);
                    __half2 hp; hp.x = __float2half(v0); hp.y = __float2half(v1);
                    *reinterpret_cast<__half2*>(Ch + (size_t)rr * ACT_W + f) = hp;
                } else {
                    float2 o; o.x = v0; o.y = v1;
                    *reinterpret_cast<float2*>(Cf + (size_t)rr * 256 + f) = o;
                }
            }
        }
    }
}

// ---------------------------------------------------------------------------
// conversions (vectorized: 8 elems / thread)
// ---------------------------------------------------------------------------
__global__ void cvt_w_one(const float* __restrict__ src,
                          __half* __restrict__ dst, int n)
{
    int i = (blockIdx.x * blockDim.x + threadIdx.x) * 8;
    if (i < n) {
        float4 a = *reinterpret_cast<const float4*>(src + i);
        float4 b = *reinterpret_cast<const float4*>(src + i + 4);
        __half2 h[4];
        h[0] = __floats2half2_rn(a.x, a.y);
        h[1] = __floats2half2_rn(a.z, a.w);
        h[2] = __floats2half2_rn(b.x, b.y);
        h[3] = __floats2half2_rn(b.z, b.w);
        *reinterpret_cast<uint4*>(dst + i) = *reinterpret_cast<uint4*>(h);
    }
}

__global__ void cvt_x_kernel(const float* __restrict__ x)
{
    int i = (blockIdx.x * blockDim.x + threadIdx.x) * 8;      // over 8192*256
    int r = i >> 8;
    int c = i & 255;
    float4 a = *reinterpret_cast<const float4*>(x + i);
    float4 b = *reinterpret_cast<const float4*>(x + i + 4);
    __half2 h[4];
    h[0] = __floats2half2_rn(a.x, a.y);
    h[1] = __floats2half2_rn(a.z, a.w);
    h[2] = __floats2half2_rn(b.x, b.y);
    h[3] = __floats2half2_rn(b.z, b.w);
    *reinterpret_cast<uint4*>(g_act + (size_t)r * ACT_W + 3072 + c) =
        *reinterpret_cast<uint4*>(h);
}

// ---------------------------------------------------------------------------
// Segmented softmax (one block per row)
// ---------------------------------------------------------------------------
__global__ void seg_softmax_kernel(const int* __restrict__ seg_ids,
                                   float* __restrict__ out)
{
    __shared__ float vals[256];
    __shared__ int   sseg[256];
    __shared__ float smax[NSEG];
    __shared__ float ssum[NSEG];

    const int row = blockIdx.x;
    const int t   = threadIdx.x;

    float v = g_logits[(size_t)row * 256 + t];
    vals[t] = v;
    sseg[t] = seg_ids[t];
    __syncthreads();

    if (t < NSEG) {
        float m = -3.402823466e+38f;
        for (int i = 0; i < 256; i++)
            if (sseg[i] == t) m = fmaxf(m, vals[i]);
        smax[t] = m;
    }
    __syncthreads();

    const int s = sseg[t];
    float e = expf(v - smax[s]);
    vals[t] = e;
    __syncthreads();

    if (t < NSEG) {
        float sum = 0.f;
        for (int i = 0; i < 256; i++)
            if (sseg[i] == t) sum += vals[i];
        ssum[t] = sum;
    }
    __syncthreads();

    out[(size_t)row * 256 + t] = e / ssum[s];
}

// ---------------------------------------------------------------------------
// Launch
// ---------------------------------------------------------------------------
#define SMEM_NT8 (NSTAGE * (128 + 256) * ROWB)   // 122880
#define SMEM_NT4 (NSTAGE * (128 + 128) * ROWB)   // 81920

extern "C" void kernel_launch(void* const* d_in, const int* in_sizes, int n_in,
                              void* d_out, int out_size)
{
    const float* x   = (const float*)d_in[0];
    const float* W0  = (const float*)d_in[1];
    const float* b0  = (const float*)d_in[2];
    const float* g0  = (const float*)d_in[3];
    const float* be0 = (const float*)d_in[4];
    const float* rm0 = (const float*)d_in[5];
    const float* rv0 = (const float*)d_in[6];
    const float* W1  = (const float*)d_in[7];
    const float* b1  = (const float*)d_in[8];
    const float* g1  = (const float*)d_in[9];
    const float* be1 = (const float*)d_in[10];
    const float* rm1 = (const float*)d_in[11];
    const float* rv1 = (const float*)d_in[12];
    const float* W2  = (const float*)d_in[13];
    const float* b2  = (const float*)d_in[14];
    const float* g2  = (const float*)d_in[15];
    const float* be2 = (const float*)d_in[16];
    const float* rm2 = (const float*)d_in[17];
    const float* rv2 = (const float*)d_in[18];
    const float* W3  = (const float*)d_in[19];
    const float* b3  = (const float*)d_in[20];
    const int*   seg = (const int*)d_in[21];

    __half *act = nullptr, *wh = nullptr;
    float* logits = nullptr;
    cudaGetSymbolAddress((void**)&act, g_act);
    cudaGetSymbolAddress((void**)&wh, g_w);
    cudaGetSymbolAddress((void**)&logits, g_logits);

    cudaFuncSetAttribute(mma_gemm<8, true>,  cudaFuncAttributeMaxDynamicSharedMemorySize, SMEM_NT8);
    cudaFuncSetAttribute(mma_gemm<4, false>, cudaFuncAttributeMaxDynamicSharedMemorySize, SMEM_NT4);

    // prologue: conversions (all sizes divisible by 8*256)
    cvt_x_kernel<<<(B_ROWS * 256) / (256 * 8), 256>>>(x);
    cvt_w_one<<<(1024 * 256) / (256 * 8), 256>>>(W0, wh + WOFF0, 1024 * 256);
    cvt_w_one<<<(1024 * 1280) / (256 * 8), 256>>>(W1, wh + WOFF1, 1024 * 1280);
    cvt_w_one<<<(1024 * 2304) / (256 * 8), 256>>>(W2, wh + WOFF2, 1024 * 2304);
    cvt_w_one<<<(256 * 3328) / (256 * 8), 256>>>(W3, wh + WOFF3, 256 * 3328);

    dim3 blk(256);
    dim3 grid256n(1024 / 256, B_ROWS / TBM);   // (4, 64) for NT=8 layers
    dim3 grid128n(256 / 128, B_ROWS / TBM);    // (2, 64) for layer 3

    mma_gemm<8, true><<<grid256n, blk, SMEM_NT8>>>(act + 3072, wh + WOFF0,
                                                   b0, g0, be0, rm0, rv0,
                                                   act + 2048, nullptr, 256);
    mma_gemm<8, true><<<grid256n, blk, SMEM_NT8>>>(act + 2048, wh + WOFF1,
                                                   b1, g1, be1, rm1, rv1,
                                                   act + 1024, nullptr, 1280);
    mma_gemm<8, true><<<grid256n, blk, SMEM_NT8>>>(act + 1024, wh + WOFF2,
                                                   b2, g2, be2, rm2, rv2,
                                                   act, nullptr, 2304);
    mma_gemm<4, false><<<grid128n, blk, SMEM_NT4>>>(act, wh + WOFF3,
                                                    b3, nullptr, nullptr, nullptr, nullptr,
                                                    nullptr, logits, 3328);

    seg_softmax_kernel<<<B_ROWS, 256>>>(seg, (float*)d_out);
}